// round 5
// baseline (speedup 1.0000x reference)
#include <cuda_runtime.h>

#define NPTS   8192
#define BATCH  4
#define TPB    128
#define QTY    8                 // ty groups (query dim)
#define QPT    8                 // queries per thread
#define QB     (QTY*QPT)         // 64 queries per block
#define NQT    (NPTS/QB)         // 128 query tiles
#define TTX    16                // tx groups (target dim)
#define TPP    16                // packed target-pairs per thread (32 targets)
#define TB     (TTX*TPP*2)       // 512 targets per block
#define NTT    (NPTS/TB)         // 16 target tiles
#define NBLK2  256

__device__ float g_qpart[NTT][BATCH][NPTS];   // pred-side partial min-s (2MB)
__device__ float g_tpart[NQT][BATCH][NPTS];   // targ-side partial min-s (16.8MB)
__device__ float g_partials[NBLK2];

__device__ __forceinline__ unsigned long long ffma2(unsigned long long a,
                                                    unsigned long long b,
                                                    unsigned long long c) {
    unsigned long long d;
    asm("fma.rn.f32x2 %0, %1, %2, %3;" : "=l"(d) : "l"(a), "l"(b), "l"(c));
    return d;
}
__device__ __forceinline__ unsigned long long mul2(unsigned long long a,
                                                   unsigned long long b) {
    unsigned long long d;
    asm("mul.rn.f32x2 %0, %1, %2;" : "=l"(d) : "l"(a), "l"(b));
    return d;
}
__device__ __forceinline__ unsigned long long add2(unsigned long long a,
                                                   unsigned long long b) {
    unsigned long long d;
    asm("add.rn.f32x2 %0, %1, %2;" : "=l"(d) : "l"(a), "l"(b));
    return d;
}
__device__ __forceinline__ unsigned long long pack2(float lo, float hi) {
    unsigned long long r;
    asm("mov.b64 %0, {%1, %2};" : "=l"(r) : "f"(lo), "f"(hi));
    return r;
}
__device__ __forceinline__ float2 unpack2(unsigned long long v) {
    float2 r;
    asm("mov.b64 {%0, %1}, %2;" : "=f"(r.x), "=f"(r.y) : "l"(v));
    return r;
}

// Block = (query-tile of 64, target-tile of 512, batch). One pass computes
// c = -p.t per pair and derives BOTH direction scores:
//   s_pt = h + c  (h = 0.5|t|^2), min over targets  -> g_qpart
//   s_tp = g + c  (g = 0.5|p|^2), min over queries  -> g_tpart
// Thread (ty,tx): 8 register queries x 16 packed target pairs from smem.
__global__ __launch_bounds__(TPB)
void chamfer_pair_kernel(const float* __restrict__ pred,
                         const float* __restrict__ targ) {
    __shared__ float4 sA[TB/2];   // (x0,x1, y0,y1) per target pair
    __shared__ float4 sB[TB/2];   // (z0,z1, h0,h1)
    __shared__ unsigned long long sRed[QTY * TTX * TPP];   // 16KB reduce buffer

    const int tid = threadIdx.x;
    const int tx  = tid & 15;
    const int ty  = tid >> 4;
    const int qt  = blockIdx.x;   // 0..127
    const int tt  = blockIdx.y;   // 0..15
    const int b   = blockIdx.z;   // 0..3

    const float* P = pred + b * 3 * NPTS;
    const float* T = targ + b * 3 * NPTS;

    // ---- stage this tile's 512 targets (one float4-group per thread) ----
    {
        const float* Tx = T + tt * TB;
        const float* Ty = Tx + NPTS;
        const float* Tz = Tx + 2 * NPTS;
        const int i = tid;                 // TB/4 == TPB
        const int m = i * 4;
        const float4 x4 = *reinterpret_cast<const float4*>(Tx + m);
        const float4 y4 = *reinterpret_cast<const float4*>(Ty + m);
        const float4 z4 = *reinterpret_cast<const float4*>(Tz + m);
        const float h0 = 0.5f * (x4.x * x4.x + y4.x * y4.x + z4.x * z4.x);
        const float h1 = 0.5f * (x4.y * x4.y + y4.y * y4.y + z4.y * z4.y);
        const float h2 = 0.5f * (x4.z * x4.z + y4.z * y4.z + z4.z * z4.z);
        const float h3 = 0.5f * (x4.w * x4.w + y4.w * y4.w + z4.w * z4.w);
        sA[2 * i]     = make_float4(x4.x, x4.y, y4.x, y4.y);
        sB[2 * i]     = make_float4(z4.x, z4.y, h0, h1);
        sA[2 * i + 1] = make_float4(x4.z, x4.w, y4.z, y4.w);
        sB[2 * i + 1] = make_float4(z4.z, z4.w, h2, h3);
    }

    // ---- load this thread's 8 register queries ----
    unsigned long long npx[QPT], npy[QPT], npz[QPT], gpk[QPT];
    float qaccl[QPT], qacch[QPT];
#pragma unroll
    for (int q = 0; q < QPT; q++) {
        const int idx = qt * QB + ty * QPT + q;
        const float x = P[idx];
        const float y = P[NPTS + idx];
        const float z = P[2 * NPTS + idx];
        npx[q] = pack2(-x, -x);
        npy[q] = pack2(-y, -y);
        npz[q] = pack2(-z, -z);
        const float g = 0.5f * (x * x + y * y + z * z);
        gpk[q] = pack2(g, g);
        qaccl[q] = 1e30f;
        qacch[q] = 1e30f;
    }
    __syncthreads();

    const ulonglong2* A  = reinterpret_cast<const ulonglong2*>(sA);
    const ulonglong2* Bq = reinterpret_cast<const ulonglong2*>(sB);

#pragma unroll 4
    for (int jj = 0; jj < TPP; ++jj) {
        const int j = tx * TPP + jj;
        const ulonglong2 av = A[j];   // (x0,x1), (y0,y1)
        const ulonglong2 bv = Bq[j];  // (z0,z1), (h0,h1)
        float tml = 1e30f, tmh = 1e30f;
#pragma unroll
        for (int q = 0; q < QPT; q++) {
            unsigned long long c = mul2(npx[q], av.x);    // c = -p.t (packed)
            c = ffma2(npy[q], av.y, c);
            c = ffma2(npz[q], bv.x, c);
            const float2 spt = unpack2(add2(bv.y, c));    // h + c
            qaccl[q] = fminf(qaccl[q], spt.x);
            qacch[q] = fminf(qacch[q], spt.y);
            const float2 stp = unpack2(add2(gpk[q], c));  // g + c
            tml = fminf(tml, stp.x);
            tmh = fminf(tmh, stp.y);
        }
        // per-(thread, target-pair) min over its 8 queries -> smem
        sRed[ty * (TTX * TPP) + tx * TPP + jj] = pack2(tml, tmh);
    }
    __syncthreads();

    // ---- t-direction: reduce over the 8 ty copies, write 512 partials ----
    {
        // 256 packed outputs; each thread handles 2
#pragma unroll
        for (int oo = 0; oo < 2; oo++) {
            const int o   = tid * 2 + oo;
            const int txo = o >> 4;
            const int jjo = o & 15;
            const float2* base = reinterpret_cast<const float2*>(sRed) +
                                 txo * TPP + jjo;
            float2 m = base[0];
#pragma unroll
            for (int t2 = 1; t2 < QTY; t2++) {
                const float2 v = base[t2 * (TTX * TPP)];
                m.x = fminf(m.x, v.x);
                m.y = fminf(m.y, v.y);
            }
            float* dst = &g_tpart[qt][b][tt * TB + txo * (2 * TPP) + jjo * 2];
            dst[0] = m.x;
            dst[1] = m.y;
        }
    }
    __syncthreads();

    // ---- q-direction: stage qacc, reduce over the 16 tx copies ----
#pragma unroll
    for (int q = 0; q < QPT; q++)
        sRed[tx * (QTY * QPT) + ty * QPT + q] = pack2(qaccl[q], qacch[q]);
    __syncthreads();

    if (tid < QB) {
        const int tyo = tid >> 3;
        const int qo  = tid & 7;
        const float2* base = reinterpret_cast<const float2*>(sRed) +
                             tyo * QPT + qo;
        float2 m = base[0];
#pragma unroll
        for (int t2 = 1; t2 < TTX; t2++) {
            const float2 v = base[t2 * (QTY * QPT)];
            m.x = fminf(m.x, v.x);
            m.y = fminf(m.y, v.y);
        }
        g_qpart[tt][b][qt * QB + tid] = fminf(m.x, m.y);
    }
}

// Combine: min over tiles, d = sqrt(|v|^2 + 2*s_min), deterministic block sums.
__global__ __launch_bounds__(256)
void chamfer_combine(const float* __restrict__ pred,
                     const float* __restrict__ targ) {
    __shared__ float red[8];
    const int tid = threadIdx.x;
    const int gp  = blockIdx.x * 256 + tid;   // 0..65535

    float s, v2;
    if (gp < BATCH * NPTS) {                  // pred side: min over target tiles
        const int b   = gp >> 13;
        const int idx = gp & (NPTS - 1);
        s = g_qpart[0][b][idx];
#pragma unroll
        for (int t = 1; t < NTT; t++) s = fminf(s, g_qpart[t][b][idx]);
        const float* P = pred + b * 3 * NPTS;
        const float x = P[idx], y = P[NPTS + idx], z = P[2 * NPTS + idx];
        v2 = x * x + y * y + z * z;
    } else {                                  // targ side: min over query tiles
        const int g2  = gp - BATCH * NPTS;
        const int b   = g2 >> 13;
        const int idx = g2 & (NPTS - 1);
        s = g_tpart[0][b][idx];
#pragma unroll 8
        for (int t = 1; t < NQT; t++) s = fminf(s, g_tpart[t][b][idx]);
        const float* T = targ + b * 3 * NPTS;
        const float x = T[idx], y = T[NPTS + idx], z = T[2 * NPTS + idx];
        v2 = x * x + y * y + z * z;
    }

    float d = sqrtf(fmaxf(fmaf(2.f, s, v2), 0.f));
#pragma unroll
    for (int off = 16; off > 0; off >>= 1)
        d += __shfl_down_sync(0xFFFFFFFFu, d, off);
    if ((tid & 31) == 0) red[tid >> 5] = d;
    __syncthreads();
    if (tid == 0) {
        float t = 0.f;
#pragma unroll
        for (int w = 0; w < 8; w++) t += red[w];
        g_partials[blockIdx.x] = t;
    }
}

// Deterministic final reduction of the 256 block partials.
__global__ void chamfer_reduce(float* __restrict__ out) {
    __shared__ float red[8];
    const int tid = threadIdx.x;
    float v = g_partials[tid];
#pragma unroll
    for (int off = 16; off > 0; off >>= 1)
        v += __shfl_down_sync(0xFFFFFFFFu, v, off);
    if ((tid & 31) == 0) red[tid >> 5] = v;
    __syncthreads();
    if (tid == 0) {
        float s = 0.f;
#pragma unroll
        for (int w = 0; w < 8; w++) s += red[w];
        out[0] = s * (1.0f / (BATCH * NPTS));
    }
}

extern "C" void kernel_launch(void* const* d_in, const int* in_sizes, int n_in,
                              void* d_out, int out_size) {
    const float* pred = (const float*)d_in[0];
    const float* targ = (const float*)d_in[1];
    float* out = (float*)d_out;

    dim3 grid(NQT, NTT, BATCH);   // 128 x 16 x 4 = 8192 blocks
    chamfer_pair_kernel<<<grid, TPB>>>(pred, targ);
    chamfer_combine<<<NBLK2, 256>>>(pred, targ);
    chamfer_reduce<<<1, 256>>>(out);
}

// round 6
// speedup vs baseline: 2.8551x; 2.8551x over previous
#include <cuda_runtime.h>

#define NPTS   8192
#define BATCH  4
#define TPB    128
#define QTY    8                 // ty groups (query dim)
#define QPT    8                 // queries per thread
#define QB     (QTY*QPT)         // 64 queries per block
#define NQT    (NPTS/QB)         // 128 query tiles
#define TTX    16                // tx groups (target dim)
#define TPP    16                // packed target-pairs per thread (32 targets)
#define TB     (TTX*TPP*2)       // 512 targets per block
#define NTT    (NPTS/TB)         // 16 target tiles
#define NPAIR  (TB/2)            // 256 target pairs per block
#define QSTR   (QTY*QPT+1)       // padded stride for q-dir smem reduce (65)
#define NBLK2  256

__device__ float g_qpart[NTT][BATCH][NPTS];   // pred-side partial min-s (2MB)
__device__ float g_tpart[NQT][BATCH][NPTS];   // targ-side partial min-s (16.8MB)
__device__ float g_partials[NBLK2];

__device__ __forceinline__ unsigned long long ffma2(unsigned long long a,
                                                    unsigned long long b,
                                                    unsigned long long c) {
    unsigned long long d;
    asm("fma.rn.f32x2 %0, %1, %2, %3;" : "=l"(d) : "l"(a), "l"(b), "l"(c));
    return d;
}
__device__ __forceinline__ unsigned long long mul2(unsigned long long a,
                                                   unsigned long long b) {
    unsigned long long d;
    asm("mul.rn.f32x2 %0, %1, %2;" : "=l"(d) : "l"(a), "l"(b));
    return d;
}
__device__ __forceinline__ unsigned long long add2(unsigned long long a,
                                                   unsigned long long b) {
    unsigned long long d;
    asm("add.rn.f32x2 %0, %1, %2;" : "=l"(d) : "l"(a), "l"(b));
    return d;
}
__device__ __forceinline__ unsigned long long pack2(float lo, float hi) {
    unsigned long long r;
    asm("mov.b64 %0, {%1, %2};" : "=l"(r) : "f"(lo), "f"(hi));
    return r;
}
__device__ __forceinline__ float2 unpack2(unsigned long long v) {
    float2 r;
    asm("mov.b64 {%0, %1}, %2;" : "=f"(r.x), "=f"(r.y) : "l"(v));
    return r;
}

// Block = (query-tile of 64, target-tile of 512, batch). One pass computes
// c = -p.t per pair and derives BOTH direction scores:
//   s_pt = h + c  (h = 0.5|t|^2), min over targets  -> g_qpart
//   s_tp = g + c  (g = 0.5|p|^2), min over queries  -> g_tpart
// Thread (ty,tx): 8 register queries x 16 packed target pairs (j = jj*16+tx,
// lane-consecutive => conflict-free LDS).
__global__ __launch_bounds__(TPB)
void chamfer_pair_kernel(const float* __restrict__ pred,
                         const float* __restrict__ targ) {
    __shared__ float4 sA[NPAIR];   // (x0,x1, y0,y1) per target pair
    __shared__ float4 sB[NPAIR];   // (z0,z1, h0,h1)
    __shared__ unsigned long long sRed[QTY * NPAIR];   // 16KB reduce buffer

    const int tid = threadIdx.x;
    const int tx  = tid & 15;
    const int ty  = tid >> 4;
    const int qt  = blockIdx.x;   // 0..127
    const int tt  = blockIdx.y;   // 0..15
    const int b   = blockIdx.z;   // 0..3

    const float* P = pred + b * 3 * NPTS;
    const float* T = targ + b * 3 * NPTS;

    // ---- stage this tile's 512 targets (one float4-group per thread) ----
    {
        const float* Tx = T + tt * TB;
        const float* Ty = Tx + NPTS;
        const float* Tz = Tx + 2 * NPTS;
        const int i = tid;                 // TB/4 == TPB
        const int m = i * 4;
        const float4 x4 = *reinterpret_cast<const float4*>(Tx + m);
        const float4 y4 = *reinterpret_cast<const float4*>(Ty + m);
        const float4 z4 = *reinterpret_cast<const float4*>(Tz + m);
        const float h0 = 0.5f * (x4.x * x4.x + y4.x * y4.x + z4.x * z4.x);
        const float h1 = 0.5f * (x4.y * x4.y + y4.y * y4.y + z4.y * z4.y);
        const float h2 = 0.5f * (x4.z * x4.z + y4.z * y4.z + z4.z * z4.z);
        const float h3 = 0.5f * (x4.w * x4.w + y4.w * y4.w + z4.w * z4.w);
        sA[2 * i]     = make_float4(x4.x, x4.y, y4.x, y4.y);   // pair 2i  = targets 4i,4i+1
        sB[2 * i]     = make_float4(z4.x, z4.y, h0, h1);
        sA[2 * i + 1] = make_float4(x4.z, x4.w, y4.z, y4.w);   // pair 2i+1 = targets 4i+2,4i+3
        sB[2 * i + 1] = make_float4(z4.z, z4.w, h2, h3);
    }

    // ---- load this thread's 8 register queries ----
    unsigned long long npx[QPT], npy[QPT], npz[QPT], gpk[QPT];
    float qaccl[QPT], qacch[QPT];
#pragma unroll
    for (int q = 0; q < QPT; q++) {
        const int idx = qt * QB + ty * QPT + q;
        const float x = P[idx];
        const float y = P[NPTS + idx];
        const float z = P[2 * NPTS + idx];
        npx[q] = pack2(-x, -x);
        npy[q] = pack2(-y, -y);
        npz[q] = pack2(-z, -z);
        const float g = 0.5f * (x * x + y * y + z * z);
        gpk[q] = pack2(g, g);
        qaccl[q] = 1e30f;
        qacch[q] = 1e30f;
    }
    __syncthreads();

    const ulonglong2* A  = reinterpret_cast<const ulonglong2*>(sA);
    const ulonglong2* Bq = reinterpret_cast<const ulonglong2*>(sB);

#pragma unroll
    for (int jj = 0; jj < TPP; ++jj) {
        const int j = jj * TTX + tx;       // lane-consecutive: conflict-free
        const ulonglong2 av = A[j];        // (x0,x1), (y0,y1)
        const ulonglong2 bv = Bq[j];       // (z0,z1), (h0,h1)
        float sl[QPT], sh[QPT];
#pragma unroll
        for (int q = 0; q < QPT; q++) {
            unsigned long long c = mul2(npx[q], av.x);    // c = -p.t (packed)
            c = ffma2(npy[q], av.y, c);
            c = ffma2(npz[q], bv.x, c);
            const float2 spt = unpack2(add2(bv.y, c));    // h + c (pred side)
            qaccl[q] = fminf(qaccl[q], spt.x);
            qacch[q] = fminf(qacch[q], spt.y);
            const float2 stp = unpack2(add2(gpk[q], c));  // g + c (targ side)
            sl[q] = stp.x;
            sh[q] = stp.y;
        }
        // tree-min over the 8 queries (depth 3)
        const float tml = fminf(fminf(fminf(sl[0], sl[1]), fminf(sl[2], sl[3])),
                                fminf(fminf(sl[4], sl[5]), fminf(sl[6], sl[7])));
        const float tmh = fminf(fminf(fminf(sh[0], sh[1]), fminf(sh[2], sh[3])),
                                fminf(fminf(sh[4], sh[5]), fminf(sh[6], sh[7])));
        sRed[ty * NPAIR + j] = pack2(tml, tmh);   // lane-consecutive STS
    }
    __syncthreads();

    // ---- t-direction: reduce over the 8 ty copies, write 512 partials ----
#pragma unroll
    for (int oo = 0; oo < 2; oo++) {
        const int o = oo * TPB + tid;       // pair index 0..255, lanes consecutive
        float2 m = unpack2(sRed[o]);
#pragma unroll
        for (int t2 = 1; t2 < QTY; t2++) {
            const float2 v = unpack2(sRed[t2 * NPAIR + o]);
            m.x = fminf(m.x, v.x);
            m.y = fminf(m.y, v.y);
        }
        float* dst = &g_tpart[qt][b][tt * TB + 2 * o];   // pair o = targets 2o,2o+1
        dst[0] = m.x;
        dst[1] = m.y;
    }
    __syncthreads();

    // ---- q-direction: stage qacc (padded stride), reduce over 16 tx copies ----
#pragma unroll
    for (int q = 0; q < QPT; q++)
        sRed[tx * QSTR + ty * QPT + q] = pack2(qaccl[q], qacch[q]);
    __syncthreads();

    if (tid < QB) {
        float2 m = unpack2(sRed[tid]);
#pragma unroll
        for (int t2 = 1; t2 < TTX; t2++) {
            const float2 v = unpack2(sRed[t2 * QSTR + tid]);
            m.x = fminf(m.x, v.x);
            m.y = fminf(m.y, v.y);
        }
        g_qpart[tt][b][qt * QB + tid] = fminf(m.x, m.y);
    }
}

// Combine: min over tiles, d = sqrt(|v|^2 + 2*s_min), deterministic block sums.
__global__ __launch_bounds__(256)
void chamfer_combine(const float* __restrict__ pred,
                     const float* __restrict__ targ) {
    __shared__ float red[8];
    const int tid = threadIdx.x;
    const int gp  = blockIdx.x * 256 + tid;   // 0..65535

    float s, v2;
    if (gp < BATCH * NPTS) {                  // pred side: min over target tiles
        const int b   = gp >> 13;
        const int idx = gp & (NPTS - 1);
        s = g_qpart[0][b][idx];
#pragma unroll
        for (int t = 1; t < NTT; t++) s = fminf(s, g_qpart[t][b][idx]);
        const float* P = pred + b * 3 * NPTS;
        const float x = P[idx], y = P[NPTS + idx], z = P[2 * NPTS + idx];
        v2 = x * x + y * y + z * z;
    } else {                                  // targ side: min over query tiles
        const int g2  = gp - BATCH * NPTS;
        const int b   = g2 >> 13;
        const int idx = g2 & (NPTS - 1);
        s = g_tpart[0][b][idx];
#pragma unroll 8
        for (int t = 1; t < NQT; t++) s = fminf(s, g_tpart[t][b][idx]);
        const float* T = targ + b * 3 * NPTS;
        const float x = T[idx], y = T[NPTS + idx], z = T[2 * NPTS + idx];
        v2 = x * x + y * y + z * z;
    }

    float d = sqrtf(fmaxf(fmaf(2.f, s, v2), 0.f));
#pragma unroll
    for (int off = 16; off > 0; off >>= 1)
        d += __shfl_down_sync(0xFFFFFFFFu, d, off);
    if ((tid & 31) == 0) red[tid >> 5] = d;
    __syncthreads();
    if (tid == 0) {
        float t = 0.f;
#pragma unroll
        for (int w = 0; w < 8; w++) t += red[w];
        g_partials[blockIdx.x] = t;
    }
}

// Deterministic final reduction of the 256 block partials.
__global__ void chamfer_reduce(float* __restrict__ out) {
    __shared__ float red[8];
    const int tid = threadIdx.x;
    float v = g_partials[tid];
#pragma unroll
    for (int off = 16; off > 0; off >>= 1)
        v += __shfl_down_sync(0xFFFFFFFFu, v, off);
    if ((tid & 31) == 0) red[tid >> 5] = v;
    __syncthreads();
    if (tid == 0) {
        float s = 0.f;
#pragma unroll
        for (int w = 0; w < 8; w++) s += red[w];
        out[0] = s * (1.0f / (BATCH * NPTS));
    }
}

extern "C" void kernel_launch(void* const* d_in, const int* in_sizes, int n_in,
                              void* d_out, int out_size) {
    const float* pred = (const float*)d_in[0];
    const float* targ = (const float*)d_in[1];
    float* out = (float*)d_out;

    dim3 grid(NQT, NTT, BATCH);   // 128 x 16 x 4 = 8192 blocks
    chamfer_pair_kernel<<<grid, TPB>>>(pred, targ);
    chamfer_combine<<<NBLK2, 256>>>(pred, targ);
    chamfer_reduce<<<1, 256>>>(out);
}